// round 7
// baseline (speedup 1.0000x reference)
#include <cuda_runtime.h>

// Problem constants (fixed by the dataset)
#define BB   64
#define NN   2048
#define EE   32768
#define DD   256
#define HH   256

#define SE      8                  // edge-pass blocks per batch
#define EPB     (EE / SE)          // 4096 edges per block
#define SPLIT_M 16                 // gather blocks per batch
#define MPB     (NN / SPLIT_M)     // 128 rows per gather block

// Scratch (__device__ globals, allocation-free). All buffers are written with
// plain stores before being read -> no init kernel needed. NOTE: these are
// only ever referenced from DEVICE code (passing them as host-side kernel
// args is invalid and was the R6 bug).
__device__ float g_wp[SE * BB * NN];         // w partials per edge-split
__device__ float g_up[SE * BB * NN];         // u partials per edge-split
__device__ float g_cp[SE * BB];              // c partials per edge-split
__device__ float g_s0p[SPLIT_M * BB * DD];   // S0 partials per gather-split
__device__ float g_s0[BB * DD];              // reduced S0
__device__ float g_c[BB];                    // reduced c
__device__ float g_v1[BB * HH];              // S1
__device__ float g_v2[BB * HH];              // pooled

// ---------------------------------------------------------------------------
// Kernel 1: w partials.  grid (BB, SE), 512 threads.
// ---------------------------------------------------------------------------
__global__ __launch_bounds__(512) void k_w(const int* __restrict__ adj_row,
                                           const int* __restrict__ adj_col,
                                           const float* __restrict__ adj_val,
                                           const int* __restrict__ curlen) {
    __shared__ float sw[NN];
    __shared__ float sc;
    int b   = blockIdx.x;
    int se  = blockIdx.y;
    int tid = threadIdx.x;

    for (int i = tid; i < NN; i += 512) sw[i] = 0.f;
    if (tid == 0) sc = 0.f;
    __syncthreads();

    int L = curlen ? *curlen : 512;
    size_t base = (size_t)b * EE + (size_t)se * EPB;
    const int4*   r4 = (const int4*)  (adj_row + base);
    const int4*   c4 = (const int4*)  (adj_col + base);
    const float4* v4 = (const float4*)(adj_val + base);
    const int NV = EPB / 4;  // 1024

    float cpart = 0.f;
    for (int i = tid; i < NV; i += 512) {
        int4 r = r4[i]; int4 c = c4[i]; float4 v = v4[i];
        if (r.x < L) { atomicAdd(&sw[c.x], v.x); cpart += v.x; }
        if (r.y < L) { atomicAdd(&sw[c.y], v.y); cpart += v.y; }
        if (r.z < L) { atomicAdd(&sw[c.z], v.z); cpart += v.z; }
        if (r.w < L) { atomicAdd(&sw[c.w], v.w); cpart += v.w; }
    }
    #pragma unroll
    for (int off = 16; off > 0; off >>= 1)
        cpart += __shfl_down_sync(0xFFFFFFFFu, cpart, off);
    if ((tid & 31) == 0) atomicAdd(&sc, cpart);
    __syncthreads();

    float* dst = g_wp + ((size_t)se * BB + b) * NN;
    for (int i = tid; i < NN; i += 512) dst[i] = sw[i];
    if (tid == 0) g_cp[se * BB + b] = sc;
}

// ---------------------------------------------------------------------------
// Kernel 2: u partials.  grid (BB, SE), 512 threads.
// ---------------------------------------------------------------------------
__global__ __launch_bounds__(512) void k_u(const int* __restrict__ adj_row,
                                           const int* __restrict__ adj_col,
                                           const float* __restrict__ adj_val) {
    __shared__ float sw[NN];
    __shared__ float su[NN];
    int b   = blockIdx.x;
    int se  = blockIdx.y;
    int tid = threadIdx.x;

    for (int i = tid; i < NN; i += 512) {
        float w = 0.f;
        #pragma unroll
        for (int s = 0; s < SE; s++)
            w += g_wp[((size_t)s * BB + b) * NN + i];
        sw[i] = w;
        su[i] = 0.f;
    }
    __syncthreads();

    size_t base = (size_t)b * EE + (size_t)se * EPB;
    const int4*   r4 = (const int4*)  (adj_row + base);
    const int4*   c4 = (const int4*)  (adj_col + base);
    const float4* v4 = (const float4*)(adj_val + base);
    const int NV = EPB / 4;

    for (int i = tid; i < NV; i += 512) {
        int4 r = r4[i]; int4 c = c4[i]; float4 v = v4[i];
        atomicAdd(&su[c.x], v.x * sw[r.x]);
        atomicAdd(&su[c.y], v.y * sw[r.y]);
        atomicAdd(&su[c.z], v.z * sw[r.z]);
        atomicAdd(&su[c.w], v.w * sw[r.w]);
    }
    __syncthreads();

    float* dst = g_up + ((size_t)se * BB + b) * NN;
    for (int i = tid; i < NN; i += 512) dst[i] = su[i];
}

// ---------------------------------------------------------------------------
// Kernel 3: S0 partials. grid (BB, SPLIT_M), 512 threads.
// ---------------------------------------------------------------------------
__global__ __launch_bounds__(512) void k_s0(const int* __restrict__ neighbors,
                                            const float* __restrict__ emb) {
    __shared__ float  su[MPB];
    __shared__ int    snb[MPB];
    __shared__ float4 red[8][64];
    int b   = blockIdx.x;
    int tid = threadIdx.x;
    int m0  = blockIdx.y * MPB;

    if (tid < MPB) {
        float u = 0.f;
        #pragma unroll
        for (int s = 0; s < SE; s++)
            u += g_up[((size_t)s * BB + b) * NN + m0 + tid];
        su[tid]  = u;
        snb[tid] = neighbors[(size_t)b * NN + m0 + tid];
    }
    __syncthreads();

    int dg = tid & 63;
    int rg = tid >> 6;   // 0..7

    float4 acc = make_float4(0.f, 0.f, 0.f, 0.f);
    #pragma unroll
    for (int i = rg; i < MPB; i += 8) {
        float u = su[i];
        const float4* row = (const float4*)(emb + (size_t)snb[i] * DD);
        float4 e = __ldg(&row[dg]);
        acc.x += u * e.x;
        acc.y += u * e.y;
        acc.z += u * e.z;
        acc.w += u * e.w;
    }
    red[rg][dg] = acc;
    __syncthreads();

    if (tid < 64) {
        float4 s = make_float4(0.f, 0.f, 0.f, 0.f);
        #pragma unroll
        for (int r = 0; r < 8; r++) {
            float4 a = red[r][tid];
            s.x += a.x; s.y += a.y; s.z += a.z; s.w += a.w;
        }
        float4* dst = (float4*)(g_s0p + ((size_t)blockIdx.y * BB + b) * DD);
        dst[tid] = s;
    }
}

// ---------------------------------------------------------------------------
// Kernel 4: reduce S0 + c partials. grid (BB), 256 threads.
// ---------------------------------------------------------------------------
__global__ __launch_bounds__(256) void k_red() {
    int b = blockIdx.x;
    int h = threadIdx.x;
    float s0 = 0.f;
    #pragma unroll
    for (int sm = 0; sm < SPLIT_M; sm++)
        s0 += g_s0p[((size_t)sm * BB + b) * DD + h];
    g_s0[(size_t)b * DD + h] = s0;
    if (h == 0) {
        float c = 0.f;
        #pragma unroll
        for (int s = 0; s < SE; s++) c += g_cp[s * BB + b];
        g_c[b] = c;
    }
}

// ---------------------------------------------------------------------------
// Kernel 5-7: batched small GEMM  C[64,256] = epi( A[64,256] @ B[256,256] ).
// grid 16 blocks (16 output cols each), 256 threads. A staged in shared with
// stride-257 padding; each block reads only its 16-column weight slice.
// A and C are selected INSIDE the kernel from the __device__ globals by MODE
// (passing __device__ globals as host-side args was the R6 bug).
// MODE 1: g_v1 = g_s0@B + c[r]*bias          (bias = b1)
// MODE 2: g_v2 = g_v1@B * (1/L) + bias       (bias = b2)
// MODE 3: out  = relu(g_v2@B + bias)         (bias = fc1b)
// ---------------------------------------------------------------------------
template<int MODE>
__global__ __launch_bounds__(256) void k_gemm(
        const float* __restrict__ Bm,
        const float* __restrict__ bias,
        const int* __restrict__ curlen,
        float* __restrict__ outp) {
    __shared__ float sA[64][257];
    int tid = threadIdx.x;
    int cb  = blockIdx.x;

    const float* A = (MODE == 1) ? g_s0 : (MODE == 2) ? g_v1 : g_v2;
    float* C       = (MODE == 1) ? g_v1 : (MODE == 2) ? g_v2 : outp;

    {
        const float4* A4 = (const float4*)A;
        #pragma unroll
        for (int k = 0; k < 16; k++) {
            int idx = tid + k * 256;     // 0..4095
            int r   = idx >> 6;
            int d4  = idx & 63;
            float4 v = A4[idx];
            sA[r][d4 * 4 + 0] = v.x;
            sA[r][d4 * 4 + 1] = v.y;
            sA[r][d4 * 4 + 2] = v.z;
            sA[r][d4 * 4 + 3] = v.w;
        }
    }
    __syncthreads();

    int r   = tid & 63;
    int cg  = tid >> 6;                 // 0..3
    int c4i = cb * 4 + cg;              // float4 column index (0..63)

    const float4* B4 = (const float4*)Bm;
    float4 acc = make_float4(0.f, 0.f, 0.f, 0.f);
    #pragma unroll 8
    for (int d = 0; d < 256; d++) {
        float a   = sA[r][d];
        float4 w  = __ldg(&B4[(size_t)d * 64 + c4i]);
        acc.x += a * w.x; acc.y += a * w.y;
        acc.z += a * w.z; acc.w += a * w.w;
    }

    float4 bb = ((const float4*)bias)[c4i];
    if (MODE == 1) {
        float cv = g_c[r];
        acc.x += cv * bb.x; acc.y += cv * bb.y;
        acc.z += cv * bb.z; acc.w += cv * bb.w;
    } else if (MODE == 2) {
        int L = curlen ? *curlen : 512;
        float invL = 1.f / (float)L;
        acc.x = acc.x * invL + bb.x; acc.y = acc.y * invL + bb.y;
        acc.z = acc.z * invL + bb.z; acc.w = acc.w * invL + bb.w;
    } else {
        acc.x += bb.x; acc.y += bb.y; acc.z += bb.z; acc.w += bb.w;
        acc.x = acc.x > 0.f ? acc.x : 0.f;
        acc.y = acc.y > 0.f ? acc.y : 0.f;
        acc.z = acc.z > 0.f ? acc.z : 0.f;
        acc.w = acc.w > 0.f ? acc.w : 0.f;
    }
    ((float4*)(C + (size_t)r * HH))[c4i] = acc;
}

// ---------------------------------------------------------------------------
extern "C" void kernel_launch(void* const* d_in, const int* in_sizes, int n_in,
                              void* d_out, int out_size) {
    const int*   neighbors = (const int*)  d_in[0];
    const int*   adj_row   = (const int*)  d_in[1];
    const int*   adj_col   = (const int*)  d_in[2];
    const float* adj_val   = (const float*)d_in[3];
    const float* emb       = (const float*)d_in[4];
    const float* W1        = (const float*)d_in[5];
    const float* b1        = (const float*)d_in[6];
    const float* W2        = (const float*)d_in[7];
    const float* b2        = (const float*)d_in[8];
    const float* fc1w      = (const float*)d_in[9];
    const float* fc1b      = (const float*)d_in[10];
    const int*   curlen    = (n_in >= 12) ? (const int*)d_in[11] : nullptr;
    float*       out       = (float*)d_out;

    k_w  <<<dim3(BB, SE), 512>>>(adj_row, adj_col, adj_val, curlen);
    k_u  <<<dim3(BB, SE), 512>>>(adj_row, adj_col, adj_val);
    k_s0 <<<dim3(BB, SPLIT_M), 512>>>(neighbors, emb);
    k_red<<<BB, 256>>>();
    k_gemm<1><<<16, 256>>>(W1,   b1,   curlen, nullptr);
    k_gemm<2><<<16, 256>>>(W2,   b2,   curlen, nullptr);
    k_gemm<3><<<16, 256>>>(fc1w, fc1b, curlen, out);
}

// round 8
// speedup vs baseline: 2.2043x; 2.2043x over previous
#include <cuda_runtime.h>

// Problem constants (fixed by the dataset)
#define BB   64
#define NN   2048
#define EE   32768
#define DD   256
#define HH   256

#define SE      4                  // edge-pass blocks per batch
#define EPB     (EE / SE)          // 8192 edges per block
#define SPLIT_M 16                 // gather blocks per batch
#define MPB     (NN / SPLIT_M)     // 128 rows per gather block

// Scratch (__device__ globals, allocation-free). All buffers are written with
// plain stores before being read -> no init kernel needed. Referenced from
// device code only.
__device__ float g_wp[SE * BB * NN];         // w partials per edge-split
__device__ float g_up[SE * BB * NN];         // u partials per edge-split
__device__ float g_cp[SE * BB];              // c partials per edge-split
__device__ float g_s0p[SPLIT_M * BB * DD];   // S0 partials per gather-split

// ---------------------------------------------------------------------------
// Kernel 1: w partials.  grid (BB, SE), 512 threads.  (identical to R5)
// ---------------------------------------------------------------------------
__global__ __launch_bounds__(512) void k_w(const int* __restrict__ adj_row,
                                           const int* __restrict__ adj_col,
                                           const float* __restrict__ adj_val,
                                           const int* __restrict__ curlen) {
    __shared__ float sw[NN];
    __shared__ float sc;
    int b   = blockIdx.x;
    int se  = blockIdx.y;
    int tid = threadIdx.x;

    for (int i = tid; i < NN; i += 512) sw[i] = 0.f;
    if (tid == 0) sc = 0.f;
    __syncthreads();

    int L = curlen ? *curlen : 512;
    size_t base = (size_t)b * EE + (size_t)se * EPB;
    const int4*   r4 = (const int4*)  (adj_row + base);
    const int4*   c4 = (const int4*)  (adj_col + base);
    const float4* v4 = (const float4*)(adj_val + base);
    const int NV = EPB / 4;  // 2048

    float cpart = 0.f;
    for (int i = tid; i < NV; i += 512) {
        int4 r = r4[i]; int4 c = c4[i]; float4 v = v4[i];
        if (r.x < L) { atomicAdd(&sw[c.x], v.x); cpart += v.x; }
        if (r.y < L) { atomicAdd(&sw[c.y], v.y); cpart += v.y; }
        if (r.z < L) { atomicAdd(&sw[c.z], v.z); cpart += v.z; }
        if (r.w < L) { atomicAdd(&sw[c.w], v.w); cpart += v.w; }
    }
    #pragma unroll
    for (int off = 16; off > 0; off >>= 1)
        cpart += __shfl_down_sync(0xFFFFFFFFu, cpart, off);
    if ((tid & 31) == 0) atomicAdd(&sc, cpart);
    __syncthreads();

    float* dst = g_wp + ((size_t)se * BB + b) * NN;
    for (int i = tid; i < NN; i += 512) dst[i] = sw[i];
    if (tid == 0) g_cp[se * BB + b] = sc;
}

// ---------------------------------------------------------------------------
// Kernel 2: u partials.  grid (BB, SE), 512 threads.  (identical to R5)
// ---------------------------------------------------------------------------
__global__ __launch_bounds__(512) void k_u(const int* __restrict__ adj_row,
                                           const int* __restrict__ adj_col,
                                           const float* __restrict__ adj_val) {
    __shared__ float sw[NN];
    __shared__ float su[NN];
    int b   = blockIdx.x;
    int se  = blockIdx.y;
    int tid = threadIdx.x;

    for (int i = tid; i < NN; i += 512) {
        float w = 0.f;
        #pragma unroll
        for (int s = 0; s < SE; s++)
            w += g_wp[((size_t)s * BB + b) * NN + i];
        sw[i] = w;
        su[i] = 0.f;
    }
    __syncthreads();

    size_t base = (size_t)b * EE + (size_t)se * EPB;
    const int4*   r4 = (const int4*)  (adj_row + base);
    const int4*   c4 = (const int4*)  (adj_col + base);
    const float4* v4 = (const float4*)(adj_val + base);
    const int NV = EPB / 4;

    for (int i = tid; i < NV; i += 512) {
        int4 r = r4[i]; int4 c = c4[i]; float4 v = v4[i];
        atomicAdd(&su[c.x], v.x * sw[r.x]);
        atomicAdd(&su[c.y], v.y * sw[r.y]);
        atomicAdd(&su[c.z], v.z * sw[r.z]);
        atomicAdd(&su[c.w], v.w * sw[r.w]);
    }
    __syncthreads();

    float* dst = g_up + ((size_t)se * BB + b) * NN;
    for (int i = tid; i < NN; i += 512) dst[i] = su[i];
}

// ---------------------------------------------------------------------------
// Kernel 3: S0 partials. grid (BB, SPLIT_M), 512 threads.  (identical to R5)
// ---------------------------------------------------------------------------
__global__ __launch_bounds__(512) void k_s0(const int* __restrict__ neighbors,
                                            const float* __restrict__ emb) {
    __shared__ float  su[MPB];
    __shared__ int    snb[MPB];
    __shared__ float4 red[8][64];
    int b   = blockIdx.x;
    int tid = threadIdx.x;
    int m0  = blockIdx.y * MPB;

    if (tid < MPB) {
        float u = 0.f;
        #pragma unroll
        for (int s = 0; s < SE; s++)
            u += g_up[((size_t)s * BB + b) * NN + m0 + tid];
        su[tid]  = u;
        snb[tid] = neighbors[(size_t)b * NN + m0 + tid];
    }
    __syncthreads();

    int dg = tid & 63;
    int rg = tid >> 6;   // 0..7

    float4 acc = make_float4(0.f, 0.f, 0.f, 0.f);
    #pragma unroll
    for (int i = rg; i < MPB; i += 8) {
        float u = su[i];
        const float4* row = (const float4*)(emb + (size_t)snb[i] * DD);
        float4 e = __ldg(&row[dg]);
        acc.x += u * e.x;
        acc.y += u * e.y;
        acc.z += u * e.z;
        acc.w += u * e.w;
    }
    red[rg][dg] = acc;
    __syncthreads();

    if (tid < 64) {
        float4 s = make_float4(0.f, 0.f, 0.f, 0.f);
        #pragma unroll
        for (int r = 0; r < 8; r++) {
            float4 a = red[r][tid];
            s.x += a.x; s.y += a.y; s.z += a.z; s.w += a.w;
        }
        float4* dst = (float4*)(g_s0p + ((size_t)blockIdx.y * BB + b) * DD);
        dst[tid] = s;
    }
}

// ---------------------------------------------------------------------------
// Kernel 4: fused 3-matvec chain, 4 BATCHES PER BLOCK, grid 16, 1024 threads.
// vs R5: each weight element is loaded once per block and feeds 4 batches
// -> weight L1 traffic 48MB -> 12MB. Thread (hq = tid&63 owns float4 of h's,
// q = tid>>6 owns 16 d's). Reduce over q in 4 short shared rounds per stage.
// Shared: sx/sy 4KB each + red 32KB + sc = ~40KB (< 48KB static limit).
// ---------------------------------------------------------------------------
__global__ __launch_bounds__(1024) void k_chain4(
        const float* __restrict__ W1, const float* __restrict__ b1,
        const float* __restrict__ W2, const float* __restrict__ b2,
        const float* __restrict__ fc1w, const float* __restrict__ fc1b,
        const int* __restrict__ curlen,
        float* __restrict__ out) {
    __shared__ float  sx[4][DD];
    __shared__ float  sy[4][HH];
    __shared__ float4 red[16][64];
    __shared__ float  sc[4];
    int g   = blockIdx.x;       // batch group: batches 4g..4g+3
    int tid = threadIdx.x;
    int hq  = tid & 63;
    int q   = tid >> 6;         // 0..15

    // Stage in reduced S0 for 4 batches (fold partial reduction here).
    {
        int bb    = tid >> 8;   // 0..3
        int h     = tid & 255;
        int batch = g * 4 + bb;
        float s0 = 0.f;
        #pragma unroll
        for (int sm = 0; sm < SPLIT_M; sm++)
            s0 += g_s0p[((size_t)sm * BB + batch) * DD + h];
        sx[bb][h] = s0;
        if (h == 0) {
            float c = 0.f;
            #pragma unroll
            for (int s = 0; s < SE; s++) c += g_cp[s * BB + batch];
            sc[bb] = c;
        }
    }
    int   L    = curlen ? __ldg(curlen) : 512;
    float invL = 1.f / (float)L;
    __syncthreads();

    // ---- stage 1: sy = sx @ W1 + c*b1 ----
    {
        const float4* W4 = (const float4*)W1;
        float4 a0 = {0,0,0,0}, a1 = {0,0,0,0}, a2 = {0,0,0,0}, a3 = {0,0,0,0};
        #pragma unroll
        for (int j = 0; j < 16; j++) {
            int d = q * 16 + j;
            float4 w = __ldg(&W4[(size_t)d * 64 + hq]);
            float x0 = sx[0][d], x1 = sx[1][d], x2 = sx[2][d], x3 = sx[3][d];
            a0.x += x0*w.x; a0.y += x0*w.y; a0.z += x0*w.z; a0.w += x0*w.w;
            a1.x += x1*w.x; a1.y += x1*w.y; a1.z += x1*w.z; a1.w += x1*w.w;
            a2.x += x2*w.x; a2.y += x2*w.y; a2.z += x2*w.z; a2.w += x2*w.w;
            a3.x += x3*w.x; a3.y += x3*w.y; a3.z += x3*w.z; a3.w += x3*w.w;
        }
        #pragma unroll
        for (int bb = 0; bb < 4; bb++) {
            red[q][hq] = (bb == 0) ? a0 : (bb == 1) ? a1 : (bb == 2) ? a2 : a3;
            __syncthreads();
            if (tid < 64) {
                float4 s = {0,0,0,0};
                #pragma unroll
                for (int r = 0; r < 16; r++) {
                    float4 a = red[r][tid];
                    s.x += a.x; s.y += a.y; s.z += a.z; s.w += a.w;
                }
                float4 bbv = ((const float4*)b1)[tid];
                float  c   = sc[bb];
                s.x += c*bbv.x; s.y += c*bbv.y; s.z += c*bbv.z; s.w += c*bbv.w;
                ((float4*)sy[bb])[tid] = s;
            }
            __syncthreads();
        }
    }

    // ---- stage 2: sx = (sy @ W2) * invL + b2 ----
    {
        const float4* W4 = (const float4*)W2;
        float4 a0 = {0,0,0,0}, a1 = {0,0,0,0}, a2 = {0,0,0,0}, a3 = {0,0,0,0};
        #pragma unroll
        for (int j = 0; j < 16; j++) {
            int d = q * 16 + j;
            float4 w = __ldg(&W4[(size_t)d * 64 + hq]);
            float x0 = sy[0][d], x1 = sy[1][d], x2 = sy[2][d], x3 = sy[3][d];
            a0.x += x0*w.x; a0.y += x0*w.y; a0.z += x0*w.z; a0.w += x0*w.w;
            a1.x += x1*w.x; a1.y += x1*w.y; a1.z += x1*w.z; a1.w += x1*w.w;
            a2.x += x2*w.x; a2.y += x2*w.y; a2.z += x2*w.z; a2.w += x2*w.w;
            a3.x += x3*w.x; a3.y += x3*w.y; a3.z += x3*w.z; a3.w += x3*w.w;
        }
        #pragma unroll
        for (int bb = 0; bb < 4; bb++) {
            red[q][hq] = (bb == 0) ? a0 : (bb == 1) ? a1 : (bb == 2) ? a2 : a3;
            __syncthreads();
            if (tid < 64) {
                float4 s = {0,0,0,0};
                #pragma unroll
                for (int r = 0; r < 16; r++) {
                    float4 a = red[r][tid];
                    s.x += a.x; s.y += a.y; s.z += a.z; s.w += a.w;
                }
                float4 bbv = ((const float4*)b2)[tid];
                s.x = s.x*invL + bbv.x; s.y = s.y*invL + bbv.y;
                s.z = s.z*invL + bbv.z; s.w = s.w*invL + bbv.w;
                ((float4*)sx[bb])[tid] = s;
            }
            __syncthreads();
        }
    }

    // ---- stage 3: out = relu(sx @ fc1w + fc1b) ----
    {
        const float4* W4 = (const float4*)fc1w;
        float4 a0 = {0,0,0,0}, a1 = {0,0,0,0}, a2 = {0,0,0,0}, a3 = {0,0,0,0};
        #pragma unroll
        for (int j = 0; j < 16; j++) {
            int d = q * 16 + j;
            float4 w = __ldg(&W4[(size_t)d * 64 + hq]);
            float x0 = sx[0][d], x1 = sx[1][d], x2 = sx[2][d], x3 = sx[3][d];
            a0.x += x0*w.x; a0.y += x0*w.y; a0.z += x0*w.z; a0.w += x0*w.w;
            a1.x += x1*w.x; a1.y += x1*w.y; a1.z += x1*w.z; a1.w += x1*w.w;
            a2.x += x2*w.x; a2.y += x2*w.y; a2.z += x2*w.z; a2.w += x2*w.w;
            a3.x += x3*w.x; a3.y += x3*w.y; a3.z += x3*w.z; a3.w += x3*w.w;
        }
        #pragma unroll
        for (int bb = 0; bb < 4; bb++) {
            red[q][hq] = (bb == 0) ? a0 : (bb == 1) ? a1 : (bb == 2) ? a2 : a3;
            __syncthreads();
            if (tid < 64) {
                float4 s = {0,0,0,0};
                #pragma unroll
                for (int r = 0; r < 16; r++) {
                    float4 a = red[r][tid];
                    s.x += a.x; s.y += a.y; s.z += a.z; s.w += a.w;
                }
                float4 bbv = ((const float4*)fc1b)[tid];
                s.x += bbv.x; s.y += bbv.y; s.z += bbv.z; s.w += bbv.w;
                s.x = s.x > 0.f ? s.x : 0.f;
                s.y = s.y > 0.f ? s.y : 0.f;
                s.z = s.z > 0.f ? s.z : 0.f;
                s.w = s.w > 0.f ? s.w : 0.f;
                int batch = g * 4 + bb;
                ((float4*)(out + (size_t)batch * HH))[tid] = s;
            }
            __syncthreads();
        }
    }
}

// ---------------------------------------------------------------------------
extern "C" void kernel_launch(void* const* d_in, const int* in_sizes, int n_in,
                              void* d_out, int out_size) {
    const int*   neighbors = (const int*)  d_in[0];
    const int*   adj_row   = (const int*)  d_in[1];
    const int*   adj_col   = (const int*)  d_in[2];
    const float* adj_val   = (const float*)d_in[3];
    const float* emb       = (const float*)d_in[4];
    const float* W1        = (const float*)d_in[5];
    const float* b1        = (const float*)d_in[6];
    const float* W2        = (const float*)d_in[7];
    const float* b2        = (const float*)d_in[8];
    const float* fc1w      = (const float*)d_in[9];
    const float* fc1b      = (const float*)d_in[10];
    const int*   curlen    = (n_in >= 12) ? (const int*)d_in[11] : nullptr;
    float*       out       = (float*)d_out;

    k_w     <<<dim3(BB, SE), 512>>>(adj_row, adj_col, adj_val, curlen);
    k_u     <<<dim3(BB, SE), 512>>>(adj_row, adj_col, adj_val);
    k_s0    <<<dim3(BB, SPLIT_M), 512>>>(neighbors, emb);
    k_chain4<<<16, 1024>>>(W1, b1, W2, b2, fc1w, fc1b, curlen, out);
}